// round 1
// baseline (speedup 1.0000x reference)
#include <cuda_runtime.h>
#include <math.h>
#include <stdint.h>

#define N_TOK 4096
#define DIMV 1024
#define HIDV 4096
#define NE 128
#define TOPKV 4
#define RNK 128
#define CAPV 256
#define M_ASSIGN (N_TOK*TOPKV)

// ---------------- device scratch (static, zero-init at module load) ----------------
__device__ float g_logits[N_TOK*NE];              // 2 MB
__device__ float g_xeff[N_TOK*DIMV];              // 16 MB
__device__ float g_h[NE*CAPV*RNK];                // 16 MB
__device__ float g_y[(size_t)NE*CAPV*HIDV];       // 512 MB
__device__ int   g_topi[M_ASSIGN];
__device__ float g_scores[M_ASSIGN];
__device__ int   g_pos[M_ASSIGN];
__device__ int   g_slot_tok[NE*CAPV];
__device__ float g_slot_s[NE*CAPV];
__device__ int   g_cnt[NE];
__device__ unsigned g_hist[256];
__device__ unsigned g_rank;
__device__ unsigned g_prefix;
__device__ float g_thr;

// ---------------- init ----------------
__global__ void init_kernel() {
    int t = threadIdx.x;
    if (t == 0) { g_rank = 419430u; g_prefix = 0u; }
    if (t < 256) g_hist[t] = 0u;
}

// ---------------- generic 128x128 SGEMM: C = A[M,K] * B[N,K]^T + bias[N] ----------------
__global__ void __launch_bounds__(256) sgemm128_kernel(
    const float* __restrict__ A, const float* __restrict__ B,
    const float* __restrict__ bias, float* __restrict__ C,
    int M, int N, int K)
{
    __shared__ float As[8][128];
    __shared__ float Bs[8][128];
    int bm = blockIdx.y * 128, bn = blockIdx.x * 128;
    int tid = threadIdx.x;
    int lr = tid >> 1;            // 0..127
    int lk = (tid & 1) * 4;       // 0 or 4
    int tx = tid & 15, ty = tid >> 4;
    const float* Ap = A + (size_t)(bm + lr) * K + lk;
    const float* Bp = B + (size_t)(bn + lr) * K + lk;
    float acc[8][8] = {};
    for (int k0 = 0; k0 < K; k0 += 8) {
        float4 a4 = *(const float4*)(Ap + k0);
        float4 b4 = *(const float4*)(Bp + k0);
        __syncthreads();
        As[lk + 0][lr] = a4.x; As[lk + 1][lr] = a4.y; As[lk + 2][lr] = a4.z; As[lk + 3][lr] = a4.w;
        Bs[lk + 0][lr] = b4.x; Bs[lk + 1][lr] = b4.y; Bs[lk + 2][lr] = b4.z; Bs[lk + 3][lr] = b4.w;
        __syncthreads();
#pragma unroll
        for (int kk = 0; kk < 8; kk++) {
            float a[8], b[8];
            *(float4*)&a[0] = *(const float4*)&As[kk][ty * 8];
            *(float4*)&a[4] = *(const float4*)&As[kk][ty * 8 + 4];
            *(float4*)&b[0] = *(const float4*)&Bs[kk][tx * 8];
            *(float4*)&b[4] = *(const float4*)&Bs[kk][tx * 8 + 4];
#pragma unroll
            for (int i = 0; i < 8; i++)
#pragma unroll
                for (int j = 0; j < 8; j++)
                    acc[i][j] += a[i] * b[j];
        }
    }
    float bb[8];
    *(float4*)&bb[0] = *(const float4*)&bias[bn + tx * 8];
    *(float4*)&bb[4] = *(const float4*)&bias[bn + tx * 8 + 4];
#pragma unroll
    for (int i = 0; i < 8; i++) {
        float* cp = C + (size_t)(bm + ty * 8 + i) * N + bn + tx * 8;
        float4 r0 = make_float4(acc[i][0] + bb[0], acc[i][1] + bb[1], acc[i][2] + bb[2], acc[i][3] + bb[3]);
        float4 r1 = make_float4(acc[i][4] + bb[4], acc[i][5] + bb[5], acc[i][6] + bb[6], acc[i][7] + bb[7]);
        *(float4*)cp = r0;
        *(float4*)(cp + 4) = r1;
    }
}

// ---------------- radix select: exact order statistic a[419430] of |logits| ----------------
__global__ void hist_kernel(int shift) {
    __shared__ unsigned h[256];
    int tid = threadIdx.x;
    h[tid] = 0u;
    __syncthreads();
    unsigned prefix = g_prefix;
#pragma unroll
    for (int j = 0; j < 4; j++) {
        int idx = (blockIdx.x * 4 + j) * 256 + tid;
        unsigned u = __float_as_uint(fabsf(g_logits[idx]));
        bool ok = (shift == 24) || ((u >> (shift + 8)) == prefix);
        if (ok) atomicAdd(&h[(u >> shift) & 255], 1u);
    }
    __syncthreads();
    atomicAdd(&g_hist[tid], h[tid]);
}

__global__ void pick_kernel(int shift) {
    unsigned rank = g_rank;
    unsigned cum = 0, b = 0;
    for (unsigned i = 0; i < 256; i++) {
        unsigned c = g_hist[i];
        if (rank < cum + c) { b = i; g_rank = rank - cum; break; }
        cum += c;
    }
    g_prefix = (g_prefix << 8) | b;
    for (int i = 0; i < 256; i++) g_hist[i] = 0u;
    if (shift == 0) g_thr = __uint_as_float(g_prefix);
}

// ---------------- top-4 (jax tie-break: desc value, asc index) + softmax ----------------
__global__ void __launch_bounds__(128) topk_kernel() {
    int warp = threadIdx.x >> 5;
    int lane = threadIdx.x & 31;
    int n = blockIdx.x * 4 + warp;
    float thr = g_thr;
    const float* row = g_logits + (size_t)n * NE;
    float v[4]; int idx[4];
#pragma unroll
    for (int j = 0; j < 4; j++) {
        int e = lane + j * 32;
        float x = row[e];
        if (fabsf(x) < thr) x = 0.0f;
        v[j] = x; idx[j] = e;
    }
    float tv[4]; int ti[4];
#pragma unroll
    for (int sel = 0; sel < 4; sel++) {
        float bv = v[0]; int bi = idx[0];
#pragma unroll
        for (int j = 1; j < 4; j++)
            if (v[j] > bv || (v[j] == bv && idx[j] < bi)) { bv = v[j]; bi = idx[j]; }
#pragma unroll
        for (int off = 16; off; off >>= 1) {
            float ov = __shfl_xor_sync(0xffffffffu, bv, off);
            int   oi = __shfl_xor_sync(0xffffffffu, bi, off);
            if (ov > bv || (ov == bv && oi < bi)) { bv = ov; bi = oi; }
        }
        tv[sel] = bv; ti[sel] = bi;
#pragma unroll
        for (int j = 0; j < 4; j++)
            if (idx[j] == bi) v[j] = -INFINITY;
    }
    float m = tv[0];
    float ex[4], sum = 0.0f;
#pragma unroll
    for (int k = 0; k < 4; k++) { ex[k] = expf(tv[k] - m); sum += ex[k]; }
    if (lane < 4) {
        g_topi[n * 4 + lane] = ti[lane];
        g_scores[n * 4 + lane] = ex[lane] / sum;
    }
}

// ---------------- xeff[n,d] = x[n,d] * sum_k s_k * diag[e_k,d] ----------------
__global__ void __launch_bounds__(256) xeff_kernel(const float* __restrict__ x,
                                                   const float* __restrict__ diag) {
    int n = blockIdx.x;
    __shared__ int se[4];
    __shared__ float ss[4];
    if (threadIdx.x < 4) {
        se[threadIdx.x] = g_topi[n * 4 + threadIdx.x];
        ss[threadIdx.x] = g_scores[n * 4 + threadIdx.x];
    }
    __syncthreads();
    const float* d0 = diag + (size_t)se[0] * DIMV;
    const float* d1 = diag + (size_t)se[1] * DIMV;
    const float* d2 = diag + (size_t)se[2] * DIMV;
    const float* d3 = diag + (size_t)se[3] * DIMV;
    float s0 = ss[0], s1 = ss[1], s2 = ss[2], s3 = ss[3];
#pragma unroll
    for (int i = 0; i < 4; i++) {
        int d = threadIdx.x + i * 256;
        float eff = s0 * d0[d] + s1 * d1[d] + s2 * d2[d] + s3 * d3[d];
        g_xeff[(size_t)n * DIMV + d] = x[(size_t)n * DIMV + d] * eff;
    }
}

// ---------------- deterministic capacity positions (matches cumsum order) ----------------
__global__ void __launch_bounds__(256) pos_kernel() {
    int e = blockIdx.x;
    int tid = threadIdx.x;
    __shared__ int sc[256];
    __shared__ int sbase;
    if (tid == 0) sbase = 0;
    __syncthreads();
    for (int chunk = 0; chunk < M_ASSIGN / 256; chunk++) {
        int m = chunk * 256 + tid;
        int flag = (g_topi[m] == e) ? 1 : 0;
        sc[tid] = flag;
        __syncthreads();
        for (int off = 1; off < 256; off <<= 1) {
            int t = (tid >= off) ? sc[tid - off] : 0;
            __syncthreads();
            sc[tid] += t;
            __syncthreads();
        }
        int pos = sbase + sc[tid] - 1;
        if (flag) {
            g_pos[m] = pos;
            if (pos < CAPV) {
                g_slot_tok[e * CAPV + pos] = m >> 2;
                g_slot_s[e * CAPV + pos] = g_scores[m];
            }
        }
        __syncthreads();
        if (tid == 255) sbase += sc[255];
        __syncthreads();
    }
    if (tid == 0) g_cnt[e] = (sbase < CAPV) ? sbase : CAPV;
}

// ---------------- GEMM1: h[e,c,r] = relu(x[tok_c,:] . W1[e,r,:] + b1[e,r]) ----------------
__global__ void __launch_bounds__(256) gemm1_kernel(const float* __restrict__ x,
                                                    const float* __restrict__ W1,
                                                    const float* __restrict__ b1) {
    int e = blockIdx.y;
    int cnt = g_cnt[e];
    int c0 = blockIdx.x * 64;
    if (c0 >= cnt) return;
    __shared__ float As[16][64];
    __shared__ float Bs[16][128];
    int tid = threadIdx.x;
    int ar = tid >> 2;            // 0..63
    int ak = (tid & 3) * 4;       // 0,4,8,12
    int c = c0 + ar;
    int tok = g_slot_tok[e * CAPV + ((c < cnt) ? c : c0)];
    const float* xrow = x + (size_t)tok * DIMV + ak;
    const float* wb = W1 + (size_t)e * RNK * DIMV;
    const float* w0 = wb + (size_t)ar * DIMV + ak;
    const float* w1p = wb + (size_t)(ar + 64) * DIMV + ak;
    int tx = tid & 15, ty = tid >> 4;
    float acc[4][8] = {};
    for (int k0 = 0; k0 < DIMV; k0 += 16) {
        float4 a4 = *(const float4*)(xrow + k0);
        float4 bA = *(const float4*)(w0 + k0);
        float4 bB = *(const float4*)(w1p + k0);
        __syncthreads();
        As[ak + 0][ar] = a4.x; As[ak + 1][ar] = a4.y; As[ak + 2][ar] = a4.z; As[ak + 3][ar] = a4.w;
        Bs[ak + 0][ar] = bA.x; Bs[ak + 1][ar] = bA.y; Bs[ak + 2][ar] = bA.z; Bs[ak + 3][ar] = bA.w;
        Bs[ak + 0][ar + 64] = bB.x; Bs[ak + 1][ar + 64] = bB.y; Bs[ak + 2][ar + 64] = bB.z; Bs[ak + 3][ar + 64] = bB.w;
        __syncthreads();
#pragma unroll
        for (int kk = 0; kk < 16; kk++) {
            float4 av = *(const float4*)&As[kk][ty * 4];
            float b[8];
            *(float4*)&b[0] = *(const float4*)&Bs[kk][tx * 8];
            *(float4*)&b[4] = *(const float4*)&Bs[kk][tx * 8 + 4];
            float a[4] = { av.x, av.y, av.z, av.w };
#pragma unroll
            for (int i = 0; i < 4; i++)
#pragma unroll
                for (int j = 0; j < 8; j++)
                    acc[i][j] += a[i] * b[j];
        }
    }
    float bb[8];
    *(float4*)&bb[0] = *(const float4*)&b1[e * RNK + tx * 8];
    *(float4*)&bb[4] = *(const float4*)&b1[e * RNK + tx * 8 + 4];
#pragma unroll
    for (int i = 0; i < 4; i++) {
        int cc = c0 + ty * 4 + i;
        if (cc < cnt) {
            float* hp = g_h + ((size_t)e * CAPV + cc) * RNK + tx * 8;
            float4 r0 = make_float4(fmaxf(acc[i][0] + bb[0], 0.f), fmaxf(acc[i][1] + bb[1], 0.f),
                                    fmaxf(acc[i][2] + bb[2], 0.f), fmaxf(acc[i][3] + bb[3], 0.f));
            float4 r1 = make_float4(fmaxf(acc[i][4] + bb[4], 0.f), fmaxf(acc[i][5] + bb[5], 0.f),
                                    fmaxf(acc[i][6] + bb[6], 0.f), fmaxf(acc[i][7] + bb[7], 0.f));
            *(float4*)hp = r0;
            *(float4*)(hp + 4) = r1;
        }
    }
}

// ---------------- GEMM2: y[e,c,h] = s_c * (h[e,c,:] . W2[e,h,:] + b2[e,h]) ----------------
__global__ void __launch_bounds__(256) gemm2_kernel(const float* __restrict__ W2,
                                                    const float* __restrict__ b2) {
    int e = blockIdx.z;
    int cnt = g_cnt[e];
    int c0 = blockIdx.y * 64;
    if (c0 >= cnt) return;
    int h0 = blockIdx.x * 128;
    __shared__ float As[16][64];
    __shared__ float Bs[16][128];
    int tid = threadIdx.x;
    int ar = tid >> 2;
    int ak = (tid & 3) * 4;
    const float* arow = g_h + ((size_t)e * CAPV + c0 + ar) * RNK + ak;
    const float* wb = W2 + (size_t)e * HIDV * RNK;
    const float* w0 = wb + (size_t)(h0 + ar) * RNK + ak;
    const float* w1p = wb + (size_t)(h0 + ar + 64) * RNK + ak;
    int tx = tid & 15, ty = tid >> 4;
    float acc[4][8] = {};
    for (int k0 = 0; k0 < RNK; k0 += 16) {
        float4 a4 = *(const float4*)(arow + k0);
        float4 bA = *(const float4*)(w0 + k0);
        float4 bB = *(const float4*)(w1p + k0);
        __syncthreads();
        As[ak + 0][ar] = a4.x; As[ak + 1][ar] = a4.y; As[ak + 2][ar] = a4.z; As[ak + 3][ar] = a4.w;
        Bs[ak + 0][ar] = bA.x; Bs[ak + 1][ar] = bA.y; Bs[ak + 2][ar] = bA.z; Bs[ak + 3][ar] = bA.w;
        Bs[ak + 0][ar + 64] = bB.x; Bs[ak + 1][ar + 64] = bB.y; Bs[ak + 2][ar + 64] = bB.z; Bs[ak + 3][ar + 64] = bB.w;
        __syncthreads();
#pragma unroll
        for (int kk = 0; kk < 16; kk++) {
            float4 av = *(const float4*)&As[kk][ty * 4];
            float b[8];
            *(float4*)&b[0] = *(const float4*)&Bs[kk][tx * 8];
            *(float4*)&b[4] = *(const float4*)&Bs[kk][tx * 8 + 4];
            float a[4] = { av.x, av.y, av.z, av.w };
#pragma unroll
            for (int i = 0; i < 4; i++)
#pragma unroll
                for (int j = 0; j < 8; j++)
                    acc[i][j] += a[i] * b[j];
        }
    }
    float bb[8];
    *(float4*)&bb[0] = *(const float4*)&b2[(size_t)e * HIDV + h0 + tx * 8];
    *(float4*)&bb[4] = *(const float4*)&b2[(size_t)e * HIDV + h0 + tx * 8 + 4];
#pragma unroll
    for (int i = 0; i < 4; i++) {
        int cc = c0 + ty * 4 + i;
        if (cc < cnt) {
            float s = g_slot_s[e * CAPV + cc];
            float* yp = g_y + ((size_t)e * CAPV + cc) * HIDV + h0 + tx * 8;
            float4 r0 = make_float4(s * (acc[i][0] + bb[0]), s * (acc[i][1] + bb[1]),
                                    s * (acc[i][2] + bb[2]), s * (acc[i][3] + bb[3]));
            float4 r1 = make_float4(s * (acc[i][4] + bb[4]), s * (acc[i][5] + bb[5]),
                                    s * (acc[i][6] + bb[6]), s * (acc[i][7] + bb[7]));
            *(float4*)yp = r0;
            *(float4*)(yp + 4) = r1;
        }
    }
}

// ---------------- combine: out[n,:] += sum_k valid_k * y[e_k, pos_k, :] ----------------
__global__ void __launch_bounds__(256) combine_kernel(float* __restrict__ out) {
    int n = blockIdx.x;
    int tid = threadIdx.x;
    __shared__ int se[4];
    __shared__ int sp[4];
    if (tid < 4) {
        se[tid] = g_topi[n * 4 + tid];
        sp[tid] = g_pos[n * 4 + tid];
    }
    __syncthreads();
#pragma unroll
    for (int it = 0; it < 4; it++) {
        int h = tid * 4 + it * 1024;
        float4 acc = *(float4*)&out[(size_t)n * HIDV + h];
#pragma unroll
        for (int k = 0; k < 4; k++) {
            if (sp[k] < CAPV) {
                float4 yv = *(const float4*)&g_y[((size_t)se[k] * CAPV + sp[k]) * HIDV + h];
                acc.x += yv.x; acc.y += yv.y; acc.z += yv.z; acc.w += yv.w;
            }
        }
        *(float4*)&out[(size_t)n * HIDV + h] = acc;
    }
}

// ---------------- host ----------------
extern "C" void kernel_launch(void* const* d_in, const int* in_sizes, int n_in,
                              void* d_out, int out_size) {
    const float* x    = (const float*)d_in[0];
    const float* Wr   = (const float*)d_in[1];
    const float* br   = (const float*)d_in[2];
    const float* diag = (const float*)d_in[3];
    const float* Wp   = (const float*)d_in[4];
    const float* bp   = (const float*)d_in[5];
    const float* W1   = (const float*)d_in[6];
    const float* b1   = (const float*)d_in[7];
    const float* W2   = (const float*)d_in[8];
    const float* b2   = (const float*)d_in[9];
    float* out = (float*)d_out;

    float* p_logits = nullptr;
    float* p_xeff = nullptr;
    cudaGetSymbolAddress((void**)&p_logits, g_logits);
    cudaGetSymbolAddress((void**)&p_xeff, g_xeff);

    init_kernel<<<1, 256>>>();

    // router logits
    sgemm128_kernel<<<dim3(1, 32), 256>>>(x, Wr, br, p_logits, N_TOK, NE, DIMV);

    // exact order statistic a[419430] of |logits| (equivalent to the lerp'd quantile predicate)
    for (int shift = 24; shift >= 0; shift -= 8) {
        hist_kernel<<<512, 256>>>(shift);
        pick_kernel<<<1, 1>>>(shift);
    }

    topk_kernel<<<N_TOK / 4, 128>>>();
    xeff_kernel<<<N_TOK, 256>>>(x, diag);
    pos_kernel<<<NE, 256>>>();

    gemm1_kernel<<<dim3(CAPV / 64, NE), 256>>>(x, W1, b1);

    // diag path writes out fully
    sgemm128_kernel<<<dim3(HIDV / 128, N_TOK / 128), 256>>>(p_xeff, Wp, bp, out, N_TOK, HIDV, DIMV);

    gemm2_kernel<<<dim3(HIDV / 128, CAPV / 64, NE), 256>>>(W2, b2);

    combine_kernel<<<N_TOK, 256>>>(out);
}

// round 2
// speedup vs baseline: 2.3359x; 2.3359x over previous
#include <cuda_runtime.h>
#include <math.h>
#include <stdint.h>

#define N_TOK 4096
#define DIMV 1024
#define HIDV 4096
#define NE 128
#define TOPKV 4
#define RNK 128
#define CAPV 256
#define M_ASSIGN (N_TOK*TOPKV)
#define LDT 36   // smem row stride (floats): conflict-free fragment reads (4*gid+tg perm)

// ---------------- device scratch (static, zero-init at module load) ----------------
__device__ float g_logits[N_TOK*NE];              // 2 MB
__device__ float g_xeff[N_TOK*DIMV];              // 16 MB
__device__ float g_h[NE*CAPV*RNK];                // 16 MB
__device__ float g_y[(size_t)NE*CAPV*HIDV];       // 512 MB
__device__ int   g_topi[M_ASSIGN];
__device__ float g_scores[M_ASSIGN];
__device__ int   g_pos[M_ASSIGN];
__device__ int   g_slot_tok[NE*CAPV];
__device__ float g_slot_s[NE*CAPV];
__device__ int   g_cnt[NE];
__device__ unsigned g_hist[256];
__device__ unsigned g_rank;
__device__ unsigned g_prefix;
__device__ float g_thr;

__device__ __forceinline__ unsigned f2tf(float f) {
    unsigned r;
    asm("cvt.rna.tf32.f32 %0, %1;" : "=r"(r) : "f"(f));
    return r;
}

__device__ __forceinline__ void mma_tf32(float* d, const unsigned* a, const unsigned* b) {
    asm volatile(
        "mma.sync.aligned.m16n8k8.row.col.f32.tf32.tf32.f32 "
        "{%0,%1,%2,%3}, {%4,%5,%6,%7}, {%8,%9}, {%0,%1,%2,%3};"
        : "+f"(d[0]), "+f"(d[1]), "+f"(d[2]), "+f"(d[3])
        : "r"(a[0]), "r"(a[1]), "r"(a[2]), "r"(a[3]), "r"(b[0]), "r"(b[1]));
}

// ---------------- init ----------------
__global__ void init_kernel() {
    int t = threadIdx.x;
    if (t == 0) { g_rank = 419430u; g_prefix = 0u; }
    if (t < 256) g_hist[t] = 0u;
}

// ---------------- fp32 SGEMM for router (exactness of top-k/quantile decisions) ----------------
__global__ void __launch_bounds__(256) sgemm128_kernel(
    const float* __restrict__ A, const float* __restrict__ B,
    const float* __restrict__ bias, float* __restrict__ C,
    int M, int N, int K)
{
    __shared__ float As[8][128];
    __shared__ float Bs[8][128];
    int bm = blockIdx.y * 128, bn = blockIdx.x * 128;
    int tid = threadIdx.x;
    int lr = tid >> 1;
    int lk = (tid & 1) * 4;
    int tx = tid & 15, ty = tid >> 4;
    const float* Ap = A + (size_t)(bm + lr) * K + lk;
    const float* Bp = B + (size_t)(bn + lr) * K + lk;
    float acc[8][8] = {};
    for (int k0 = 0; k0 < K; k0 += 8) {
        float4 a4 = *(const float4*)(Ap + k0);
        float4 b4 = *(const float4*)(Bp + k0);
        __syncthreads();
        As[lk + 0][lr] = a4.x; As[lk + 1][lr] = a4.y; As[lk + 2][lr] = a4.z; As[lk + 3][lr] = a4.w;
        Bs[lk + 0][lr] = b4.x; Bs[lk + 1][lr] = b4.y; Bs[lk + 2][lr] = b4.z; Bs[lk + 3][lr] = b4.w;
        __syncthreads();
#pragma unroll
        for (int kk = 0; kk < 8; kk++) {
            float a[8], b[8];
            *(float4*)&a[0] = *(const float4*)&As[kk][ty * 8];
            *(float4*)&a[4] = *(const float4*)&As[kk][ty * 8 + 4];
            *(float4*)&b[0] = *(const float4*)&Bs[kk][tx * 8];
            *(float4*)&b[4] = *(const float4*)&Bs[kk][tx * 8 + 4];
#pragma unroll
            for (int i = 0; i < 8; i++)
#pragma unroll
                for (int j = 0; j < 8; j++)
                    acc[i][j] += a[i] * b[j];
        }
    }
    float bb[8];
    *(float4*)&bb[0] = *(const float4*)&bias[bn + tx * 8];
    *(float4*)&bb[4] = *(const float4*)&bias[bn + tx * 8 + 4];
#pragma unroll
    for (int i = 0; i < 8; i++) {
        float* cp = C + (size_t)(bm + ty * 8 + i) * N + bn + tx * 8;
        float4 r0 = make_float4(acc[i][0] + bb[0], acc[i][1] + bb[1], acc[i][2] + bb[2], acc[i][3] + bb[3]);
        float4 r1 = make_float4(acc[i][4] + bb[4], acc[i][5] + bb[5], acc[i][6] + bb[6], acc[i][7] + bb[7]);
        *(float4*)cp = r0;
        *(float4*)(cp + 4) = r1;
    }
}

// ---------------- tf32 tensor-core GEMM: C = A[M,K] * B[N,K]^T (+bias, per-mode epilogue) ----
// MODE 0: diag path   (A=xeff,  B=Wp, bias=bp, C=out,  N=4096)
// MODE 1: LoRA down   (A=x gathered via slot_tok, B=W1[e], bias=b1[e], relu, C=g_h, N=128)
// MODE 2: LoRA up     (A=g_h[e], B=W2[e], bias=b2[e], scale by slot_s, C=g_y, N=4096)
template<int MODE, int KDIM>
__global__ void __launch_bounds__(256) mma_gemm_kernel(
    const float* __restrict__ Ain, const float* __restrict__ Bin,
    const float* __restrict__ bias, float* __restrict__ Cout, int Ncols)
{
    __shared__ float As[128 * LDT];
    __shared__ float Bs[128 * LDT];

    const int e = (MODE == 0) ? 0 : blockIdx.z;
    int bm, bn;
    const float* A = Ain;
    const float* B = Bin;
    const float* bp = bias;
    float* C = Cout;
    if (MODE == 0) {
        bm = blockIdx.y * 128; bn = blockIdx.x * 128;
    } else {
        int cnt = g_cnt[e];
        bm = blockIdx.y * 128;
        if (bm >= cnt) return;
        bn = blockIdx.x * 128;
        if (MODE == 1) {
            B = Bin + (size_t)e * RNK * KDIM;
            bp = bias + e * RNK;
            C = Cout + (size_t)e * CAPV * RNK;
        } else {
            A = Ain + (size_t)e * CAPV * RNK;
            B = Bin + (size_t)e * HIDV * RNK;
            bp = bias + (size_t)e * HIDV;
            C = Cout + (size_t)e * CAPV * HIDV;
        }
    }

    const int tid = threadIdx.x;
    // gmem->smem loader mapping: each thread owns 4 float4 (rows idx>>3, col4 idx&7)
    const float* Arow[4];
    const float* Brow[4];
    int soff[4];
#pragma unroll
    for (int i = 0; i < 4; i++) {
        int idx = tid + i * 256;
        int r = idx >> 3;
        int c = (idx & 7) * 4;
        int grow;
        if (MODE == 1) grow = g_slot_tok[e * CAPV + bm + r];
        else grow = bm + r;
        Arow[i] = A + (size_t)grow * KDIM + c;
        Brow[i] = B + (size_t)(bn + r) * KDIM + c;
        soff[i] = r * LDT + c;
    }

    const int wid = tid >> 5, lane = tid & 31;
    const int wm = (wid & 1) * 64;     // warp M offset within tile
    const int wn = (wid >> 1) * 32;    // warp N offset within tile
    const int gid = lane >> 2, tg = lane & 3;

    float acc[4][4][4] = {};   // [mi][ni][frag]

    for (int k0 = 0; k0 < KDIM; k0 += 32) {
        float4 va[4], vb[4];
#pragma unroll
        for (int i = 0; i < 4; i++) {
            va[i] = *(const float4*)(Arow[i] + k0);
            vb[i] = *(const float4*)(Brow[i] + k0);
        }
        __syncthreads();
#pragma unroll
        for (int i = 0; i < 4; i++) {
            float* pa = &As[soff[i]];
            pa[0] = __uint_as_float(f2tf(va[i].x));
            pa[1] = __uint_as_float(f2tf(va[i].y));
            pa[2] = __uint_as_float(f2tf(va[i].z));
            pa[3] = __uint_as_float(f2tf(va[i].w));
            float* pb = &Bs[soff[i]];
            pb[0] = __uint_as_float(f2tf(vb[i].x));
            pb[1] = __uint_as_float(f2tf(vb[i].y));
            pb[2] = __uint_as_float(f2tf(vb[i].z));
            pb[3] = __uint_as_float(f2tf(vb[i].w));
        }
        __syncthreads();
#pragma unroll
        for (int kk = 0; kk < 4; kk++) {
            int kb = kk * 8;
            unsigned afr[4][4];
#pragma unroll
            for (int mi = 0; mi < 4; mi++) {
                int rb = wm + mi * 16;
                afr[mi][0] = __float_as_uint(As[(rb + gid) * LDT + kb + tg]);
                afr[mi][1] = __float_as_uint(As[(rb + gid + 8) * LDT + kb + tg]);
                afr[mi][2] = __float_as_uint(As[(rb + gid) * LDT + kb + tg + 4]);
                afr[mi][3] = __float_as_uint(As[(rb + gid + 8) * LDT + kb + tg + 4]);
            }
            unsigned bfr[4][2];
#pragma unroll
            for (int ni = 0; ni < 4; ni++) {
                int nb = wn + ni * 8;
                bfr[ni][0] = __float_as_uint(Bs[(nb + gid) * LDT + kb + tg]);
                bfr[ni][1] = __float_as_uint(Bs[(nb + gid) * LDT + kb + tg + 4]);
            }
#pragma unroll
            for (int mi = 0; mi < 4; mi++)
#pragma unroll
                for (int ni = 0; ni < 4; ni++)
                    mma_tf32(acc[mi][ni], afr[mi], bfr[ni]);
        }
    }

    // epilogue
#pragma unroll
    for (int mi = 0; mi < 4; mi++) {
        int row0 = wm + mi * 16 + gid;
        int row1 = row0 + 8;
        float s0 = 1.0f, s1 = 1.0f;
        if (MODE == 2) {
            s0 = g_slot_s[e * CAPV + bm + row0];
            s1 = g_slot_s[e * CAPV + bm + row1];
        }
#pragma unroll
        for (int ni = 0; ni < 4; ni++) {
            int colg = bn + wn + ni * 8 + tg * 2;
            float2 bb = *(const float2*)&bp[colg];
            float v0 = acc[mi][ni][0] + bb.x;
            float v1 = acc[mi][ni][1] + bb.y;
            float v2 = acc[mi][ni][2] + bb.x;
            float v3 = acc[mi][ni][3] + bb.y;
            if (MODE == 1) {
                v0 = fmaxf(v0, 0.f); v1 = fmaxf(v1, 0.f);
                v2 = fmaxf(v2, 0.f); v3 = fmaxf(v3, 0.f);
            } else if (MODE == 2) {
                v0 *= s0; v1 *= s0; v2 *= s1; v3 *= s1;
            }
            float2* p0 = (float2*)&C[(size_t)(bm + row0) * Ncols + colg];
            float2* p1 = (float2*)&C[(size_t)(bm + row1) * Ncols + colg];
            *p0 = make_float2(v0, v1);
            *p1 = make_float2(v2, v3);
        }
    }
}

// ---------------- radix select: exact order statistic a[419430] of |logits| ----------------
__global__ void hist_kernel(int shift) {
    __shared__ unsigned h[256];
    int tid = threadIdx.x;
    h[tid] = 0u;
    __syncthreads();
    unsigned prefix = g_prefix;
#pragma unroll
    for (int j = 0; j < 4; j++) {
        int idx = (blockIdx.x * 4 + j) * 256 + tid;
        unsigned u = __float_as_uint(fabsf(g_logits[idx]));
        bool ok = (shift == 24) || ((u >> (shift + 8)) == prefix);
        if (ok) atomicAdd(&h[(u >> shift) & 255], 1u);
    }
    __syncthreads();
    atomicAdd(&g_hist[tid], h[tid]);
}

__global__ void pick_kernel(int shift) {
    unsigned rank = g_rank;
    unsigned cum = 0, b = 0;
    for (unsigned i = 0; i < 256; i++) {
        unsigned c = g_hist[i];
        if (rank < cum + c) { b = i; g_rank = rank - cum; break; }
        cum += c;
    }
    g_prefix = (g_prefix << 8) | b;
    for (int i = 0; i < 256; i++) g_hist[i] = 0u;
    if (shift == 0) g_thr = __uint_as_float(g_prefix);
}

// ---------------- top-4 (jax tie-break: desc value, asc index) + softmax ----------------
__global__ void __launch_bounds__(128) topk_kernel() {
    int warp = threadIdx.x >> 5;
    int lane = threadIdx.x & 31;
    int n = blockIdx.x * 4 + warp;
    float thr = g_thr;
    const float* row = g_logits + (size_t)n * NE;
    float v[4]; int idx[4];
#pragma unroll
    for (int j = 0; j < 4; j++) {
        int e = lane + j * 32;
        float x = row[e];
        if (fabsf(x) < thr) x = 0.0f;
        v[j] = x; idx[j] = e;
    }
    float tv[4]; int ti[4];
#pragma unroll
    for (int sel = 0; sel < 4; sel++) {
        float bv = v[0]; int bi = idx[0];
#pragma unroll
        for (int j = 1; j < 4; j++)
            if (v[j] > bv || (v[j] == bv && idx[j] < bi)) { bv = v[j]; bi = idx[j]; }
#pragma unroll
        for (int off = 16; off; off >>= 1) {
            float ov = __shfl_xor_sync(0xffffffffu, bv, off);
            int   oi = __shfl_xor_sync(0xffffffffu, bi, off);
            if (ov > bv || (ov == bv && oi < bi)) { bv = ov; bi = oi; }
        }
        tv[sel] = bv; ti[sel] = bi;
#pragma unroll
        for (int j = 0; j < 4; j++)
            if (idx[j] == bi) v[j] = -INFINITY;
    }
    float m = tv[0];
    float ex[4], sum = 0.0f;
#pragma unroll
    for (int k = 0; k < 4; k++) { ex[k] = expf(tv[k] - m); sum += ex[k]; }
    if (lane < 4) {
        g_topi[n * 4 + lane] = ti[lane];
        g_scores[n * 4 + lane] = ex[lane] / sum;
    }
}

// ---------------- xeff[n,d] = x[n,d] * sum_k s_k * diag[e_k,d] ----------------
__global__ void __launch_bounds__(256) xeff_kernel(const float* __restrict__ x,
                                                   const float* __restrict__ diag) {
    int n = blockIdx.x;
    __shared__ int se[4];
    __shared__ float ss[4];
    if (threadIdx.x < 4) {
        se[threadIdx.x] = g_topi[n * 4 + threadIdx.x];
        ss[threadIdx.x] = g_scores[n * 4 + threadIdx.x];
    }
    __syncthreads();
    const float* d0 = diag + (size_t)se[0] * DIMV;
    const float* d1 = diag + (size_t)se[1] * DIMV;
    const float* d2 = diag + (size_t)se[2] * DIMV;
    const float* d3 = diag + (size_t)se[3] * DIMV;
    float s0 = ss[0], s1 = ss[1], s2 = ss[2], s3 = ss[3];
#pragma unroll
    for (int i = 0; i < 4; i++) {
        int d = threadIdx.x + i * 256;
        float eff = s0 * d0[d] + s1 * d1[d] + s2 * d2[d] + s3 * d3[d];
        g_xeff[(size_t)n * DIMV + d] = x[(size_t)n * DIMV + d] * eff;
    }
}

// ---------------- deterministic capacity positions (matches cumsum order) ----------------
__global__ void __launch_bounds__(256) pos_kernel() {
    int e = blockIdx.x;
    int tid = threadIdx.x;
    __shared__ int sc[256];
    __shared__ int sbase;
    if (tid == 0) sbase = 0;
    __syncthreads();
    for (int chunk = 0; chunk < M_ASSIGN / 256; chunk++) {
        int m = chunk * 256 + tid;
        int flag = (g_topi[m] == e) ? 1 : 0;
        sc[tid] = flag;
        __syncthreads();
        for (int off = 1; off < 256; off <<= 1) {
            int t = (tid >= off) ? sc[tid - off] : 0;
            __syncthreads();
            sc[tid] += t;
            __syncthreads();
        }
        int pos = sbase + sc[tid] - 1;
        if (flag) {
            g_pos[m] = pos;
            if (pos < CAPV) {
                g_slot_tok[e * CAPV + pos] = m >> 2;
                g_slot_s[e * CAPV + pos] = g_scores[m];
            }
        }
        __syncthreads();
        if (tid == 255) sbase += sc[255];
        __syncthreads();
    }
    if (tid == 0) g_cnt[e] = (sbase < CAPV) ? sbase : CAPV;
}

// ---------------- combine: out[n,:] += sum_k valid_k * y[e_k, pos_k, :] ----------------
__global__ void __launch_bounds__(256) combine_kernel(float* __restrict__ out) {
    int n = blockIdx.x;
    int tid = threadIdx.x;
    __shared__ int se[4];
    __shared__ int sp[4];
    if (tid < 4) {
        se[tid] = g_topi[n * 4 + tid];
        sp[tid] = g_pos[n * 4 + tid];
    }
    __syncthreads();
#pragma unroll
    for (int it = 0; it < 4; it++) {
        int h = tid * 4 + it * 1024;
        float4 acc = *(float4*)&out[(size_t)n * HIDV + h];
#pragma unroll
        for (int k = 0; k < 4; k++) {
            if (sp[k] < CAPV) {
                float4 yv = *(const float4*)&g_y[((size_t)se[k] * CAPV + sp[k]) * HIDV + h];
                acc.x += yv.x; acc.y += yv.y; acc.z += yv.z; acc.w += yv.w;
            }
        }
        *(float4*)&out[(size_t)n * HIDV + h] = acc;
    }
}

// ---------------- host ----------------
extern "C" void kernel_launch(void* const* d_in, const int* in_sizes, int n_in,
                              void* d_out, int out_size) {
    const float* x    = (const float*)d_in[0];
    const float* Wr   = (const float*)d_in[1];
    const float* br   = (const float*)d_in[2];
    const float* diag = (const float*)d_in[3];
    const float* Wp   = (const float*)d_in[4];
    const float* bp   = (const float*)d_in[5];
    const float* W1   = (const float*)d_in[6];
    const float* b1   = (const float*)d_in[7];
    const float* W2   = (const float*)d_in[8];
    const float* b2   = (const float*)d_in[9];
    float* out = (float*)d_out;

    float* p_logits = nullptr;
    float* p_xeff = nullptr;
    float* p_h = nullptr;
    float* p_y = nullptr;
    cudaGetSymbolAddress((void**)&p_logits, g_logits);
    cudaGetSymbolAddress((void**)&p_xeff, g_xeff);
    cudaGetSymbolAddress((void**)&p_h, g_h);
    cudaGetSymbolAddress((void**)&p_y, g_y);

    init_kernel<<<1, 256>>>();

    // router logits (exact fp32 — discrete decisions depend on these)
    sgemm128_kernel<<<dim3(1, 32), 256>>>(x, Wr, br, p_logits, N_TOK, NE, DIMV);

    // exact order statistic a[419430] of |logits|
    for (int shift = 24; shift >= 0; shift -= 8) {
        hist_kernel<<<512, 256>>>(shift);
        pick_kernel<<<1, 1>>>(shift);
    }

    topk_kernel<<<N_TOK / 4, 128>>>();
    xeff_kernel<<<N_TOK, 256>>>(x, diag);
    pos_kernel<<<NE, 256>>>();

    // LoRA down: h = relu(x_gathered @ W1^T + b1)   [tf32 tensor core]
    mma_gemm_kernel<1, DIMV><<<dim3(1, CAPV / 128, NE), 256>>>(x, W1, b1, p_h, RNK);

    // diag path: out = xeff @ Wp^T + bp             [tf32 tensor core]
    mma_gemm_kernel<0, DIMV><<<dim3(HIDV / 128, N_TOK / 128), 256>>>(p_xeff, Wp, bp, out, HIDV);

    // LoRA up: y = s * (h @ W2^T + b2)              [tf32 tensor core]
    mma_gemm_kernel<2, RNK><<<dim3(HIDV / 128, CAPV / 128, NE), 256>>>(p_h, W2, b2, p_y, HIDV);

    combine_kernel<<<N_TOK, 256>>>(out);
}

// round 3
// speedup vs baseline: 2.8640x; 1.2261x over previous
#include <cuda_runtime.h>
#include <math.h>
#include <stdint.h>

#define N_TOK 4096
#define DIMV 1024
#define HIDV 4096
#define NE 128
#define TOPKV 4
#define RNK 128
#define CAPV 256
#define M_ASSIGN (N_TOK*TOPKV)
#define LDT 36   // smem row stride (floats): conflict-free fragment reads

// ---------------- device scratch (static, zero-init at module load) ----------------
__device__ float g_logits[N_TOK*NE];               // 2 MB
__device__ float g_xeff[N_TOK*DIMV];               // 16 MB
__device__ float g_h[NE*CAPV*RNK];                 // 16 MB
__device__ float g_ya[(size_t)M_ASSIGN*HIDV];      // 256 MB, token-major LoRA outputs
__device__ int   g_topi[M_ASSIGN];
__device__ float g_scores[M_ASSIGN];
__device__ int   g_pos[M_ASSIGN];
__device__ int   g_slot_tok[NE*CAPV];
__device__ int   g_slot_m[NE*CAPV];
__device__ float g_slot_s[NE*CAPV];
__device__ int   g_cnt[NE];
__device__ unsigned g_hist[256];
__device__ unsigned g_rank;
__device__ unsigned g_prefix;
__device__ float g_thr;

__device__ __forceinline__ unsigned f2tf(float f) {
    unsigned r;
    asm("cvt.rna.tf32.f32 %0, %1;" : "=r"(r) : "f"(f));
    return r;
}

__device__ __forceinline__ void mma_tf32(float* d, const unsigned* a, const unsigned* b) {
    asm volatile(
        "mma.sync.aligned.m16n8k8.row.col.f32.tf32.tf32.f32 "
        "{%0,%1,%2,%3}, {%4,%5,%6,%7}, {%8,%9}, {%0,%1,%2,%3};"
        : "+f"(d[0]), "+f"(d[1]), "+f"(d[2]), "+f"(d[3])
        : "r"(a[0]), "r"(a[1]), "r"(a[2]), "r"(a[3]), "r"(b[0]), "r"(b[1]));
}

// ---------------- init ----------------
__global__ void init_kernel() {
    int t = threadIdx.x;
    if (t == 0) { g_rank = 419430u; g_prefix = 0u; }
    if (t < 256) g_hist[t] = 0u;
}

// ---------------- router: fp32 SIMT 64x64 tiles (exact decisions), grid (N/64, M/64) ------
__global__ void __launch_bounds__(256) router_kernel(
    const float* __restrict__ A, const float* __restrict__ B,
    const float* __restrict__ bias, float* __restrict__ C)
{
    const int K = DIMV, N = NE;
    __shared__ float As[16][68];
    __shared__ float Bs[16][68];
    int bm = blockIdx.y * 64, bn = blockIdx.x * 64;
    int tid = threadIdx.x;
    int lr = tid >> 2;            // 0..63
    int lc = (tid & 3) * 4;       // 0,4,8,12
    int tx = tid & 15, ty = tid >> 4;
    const float* Ap = A + (size_t)(bm + lr) * K + lc;
    const float* Bp = B + (size_t)(bn + lr) * K + lc;
    float acc[4][4] = {};
    for (int k0 = 0; k0 < K; k0 += 16) {
        float4 a4 = *(const float4*)(Ap + k0);
        float4 b4 = *(const float4*)(Bp + k0);
        __syncthreads();
        As[lc + 0][lr] = a4.x; As[lc + 1][lr] = a4.y; As[lc + 2][lr] = a4.z; As[lc + 3][lr] = a4.w;
        Bs[lc + 0][lr] = b4.x; Bs[lc + 1][lr] = b4.y; Bs[lc + 2][lr] = b4.z; Bs[lc + 3][lr] = b4.w;
        __syncthreads();
#pragma unroll
        for (int kk = 0; kk < 16; kk++) {
            float4 av = *(const float4*)&As[kk][ty * 4];
            float4 bv = *(const float4*)&Bs[kk][tx * 4];
            float a[4] = { av.x, av.y, av.z, av.w };
            float b[4] = { bv.x, bv.y, bv.z, bv.w };
#pragma unroll
            for (int i = 0; i < 4; i++)
#pragma unroll
                for (int j = 0; j < 4; j++)
                    acc[i][j] += a[i] * b[j];
        }
    }
    float4 bb = *(const float4*)&bias[bn + tx * 4];
    float b[4] = { bb.x, bb.y, bb.z, bb.w };
#pragma unroll
    for (int i = 0; i < 4; i++) {
        float* cp = C + (size_t)(bm + ty * 4 + i) * N + bn + tx * 4;
        *(float4*)cp = make_float4(acc[i][0] + b[0], acc[i][1] + b[1], acc[i][2] + b[2], acc[i][3] + b[3]);
    }
}

// ---------------- tf32 tensor-core GEMM family ----------------
// MODE 0: diag path + fused LoRA combine (A=xeff, B=Wp, bias=bp, C=out)
// MODE 1: LoRA down (A=x gathered, B=W1[e], bias=b1[e], relu -> g_h)
// MODE 2: LoRA up   (A=g_h[e], B=W2[e], bias=b2[e], scale by slot_s -> g_ya[m])
template<int MODE, int KDIM>
__global__ void __launch_bounds__(256) mma_gemm_kernel(
    const float* __restrict__ Ain, const float* __restrict__ Bin,
    const float* __restrict__ bias, float* __restrict__ Cout, int Ncols)
{
    __shared__ float As[128 * LDT];
    __shared__ float Bs[128 * LDT];
    __shared__ int sm_pos[512];

    const int e = (MODE == 0) ? 0 : blockIdx.z;
    int bm, bn;
    const float* A = Ain;
    const float* B = Bin;
    const float* bp = bias;
    int cnt = 0;
    if (MODE == 0) {
        bm = blockIdx.y * 128; bn = blockIdx.x * 128;
    } else {
        cnt = g_cnt[e];
        bm = blockIdx.y * 128;
        if (bm >= cnt) return;
        bn = blockIdx.x * 128;
        if (MODE == 1) {
            B = Bin + (size_t)e * RNK * KDIM;
            bp = bias + e * RNK;
        } else {
            A = Ain + (size_t)e * CAPV * RNK;
            B = Bin + (size_t)e * HIDV * RNK;
            bp = bias + (size_t)e * HIDV;
        }
    }

    const int tid = threadIdx.x;
    const float* Arow[4];
    const float* Brow[4];
    int soff[4];
#pragma unroll
    for (int i = 0; i < 4; i++) {
        int idx = tid + i * 256;
        int r = idx >> 3;
        int c = (idx & 7) * 4;
        int grow;
        if (MODE == 1) grow = g_slot_tok[e * CAPV + bm + r];
        else grow = bm + r;
        Arow[i] = A + (size_t)grow * KDIM + c;
        Brow[i] = B + (size_t)(bn + r) * KDIM + c;
        soff[i] = r * LDT + c;
    }

    const int wid = tid >> 5, lane = tid & 31;
    const int wm = (wid & 1) * 64;
    const int wn = (wid >> 1) * 32;
    const int gid = lane >> 2, tg = lane & 3;

    float acc[4][4][4] = {};

    for (int k0 = 0; k0 < KDIM; k0 += 32) {
        float4 va[4], vb[4];
#pragma unroll
        for (int i = 0; i < 4; i++) {
            va[i] = *(const float4*)(Arow[i] + k0);
            vb[i] = *(const float4*)(Brow[i] + k0);
        }
        __syncthreads();
#pragma unroll
        for (int i = 0; i < 4; i++) {
            float* pa = &As[soff[i]];
            pa[0] = __uint_as_float(f2tf(va[i].x));
            pa[1] = __uint_as_float(f2tf(va[i].y));
            pa[2] = __uint_as_float(f2tf(va[i].z));
            pa[3] = __uint_as_float(f2tf(va[i].w));
            float* pb = &Bs[soff[i]];
            pb[0] = __uint_as_float(f2tf(vb[i].x));
            pb[1] = __uint_as_float(f2tf(vb[i].y));
            pb[2] = __uint_as_float(f2tf(vb[i].z));
            pb[3] = __uint_as_float(f2tf(vb[i].w));
        }
        __syncthreads();
#pragma unroll
        for (int kk = 0; kk < 4; kk++) {
            int kb = kk * 8;
            unsigned afr[4][4];
#pragma unroll
            for (int mi = 0; mi < 4; mi++) {
                int rb = wm + mi * 16;
                afr[mi][0] = __float_as_uint(As[(rb + gid) * LDT + kb + tg]);
                afr[mi][1] = __float_as_uint(As[(rb + gid + 8) * LDT + kb + tg]);
                afr[mi][2] = __float_as_uint(As[(rb + gid) * LDT + kb + tg + 4]);
                afr[mi][3] = __float_as_uint(As[(rb + gid + 8) * LDT + kb + tg + 4]);
            }
            unsigned bfr[4][2];
#pragma unroll
            for (int ni = 0; ni < 4; ni++) {
                int nb = wn + ni * 8;
                bfr[ni][0] = __float_as_uint(Bs[(nb + gid) * LDT + kb + tg]);
                bfr[ni][1] = __float_as_uint(Bs[(nb + gid) * LDT + kb + tg + 4]);
            }
#pragma unroll
            for (int mi = 0; mi < 4; mi++)
#pragma unroll
                for (int ni = 0; ni < 4; ni++)
                    mma_tf32(acc[mi][ni], afr[mi], bfr[ni]);
        }
    }

    // stage per-row assignment validity for the fused combine (MODE 0)
    if (MODE == 0) {
        for (int i = tid; i < 512; i += 256)
            sm_pos[i] = g_pos[(bm + (i >> 2)) * 4 + (i & 3)];
        __syncthreads();
    }

    // epilogue
#pragma unroll
    for (int mi = 0; mi < 4; mi++) {
        int row0 = wm + mi * 16 + gid;
        int row1 = row0 + 8;
        if (MODE == 0) {
#pragma unroll
            for (int ni = 0; ni < 4; ni++) {
                int colg = bn + wn + ni * 8 + tg * 2;
                float2 bb = *(const float2*)&bp[colg];
                float v0 = acc[mi][ni][0] + bb.x;
                float v1 = acc[mi][ni][1] + bb.y;
                float v2 = acc[mi][ni][2] + bb.x;
                float v3 = acc[mi][ni][3] + bb.y;
#pragma unroll
                for (int k = 0; k < 4; k++) {
                    if (sm_pos[row0 * 4 + k] < CAPV) {
                        float2 yv = *(const float2*)&g_ya[((size_t)((bm + row0) * 4 + k)) * HIDV + colg];
                        v0 += yv.x; v1 += yv.y;
                    }
                    if (sm_pos[row1 * 4 + k] < CAPV) {
                        float2 yv = *(const float2*)&g_ya[((size_t)((bm + row1) * 4 + k)) * HIDV + colg];
                        v2 += yv.x; v3 += yv.y;
                    }
                }
                *(float2*)&Cout[(size_t)(bm + row0) * Ncols + colg] = make_float2(v0, v1);
                *(float2*)&Cout[(size_t)(bm + row1) * Ncols + colg] = make_float2(v2, v3);
            }
        } else if (MODE == 1) {
#pragma unroll
            for (int ni = 0; ni < 4; ni++) {
                int colg = bn + wn + ni * 8 + tg * 2;
                float2 bb = *(const float2*)&bp[colg];
                int cc0 = bm + row0, cc1 = bm + row1;
                if (cc0 < cnt) {
                    float* p = &g_h[((size_t)e * CAPV + cc0) * RNK + colg];
                    *(float2*)p = make_float2(fmaxf(acc[mi][ni][0] + bb.x, 0.f),
                                              fmaxf(acc[mi][ni][1] + bb.y, 0.f));
                }
                if (cc1 < cnt) {
                    float* p = &g_h[((size_t)e * CAPV + cc1) * RNK + colg];
                    *(float2*)p = make_float2(fmaxf(acc[mi][ni][2] + bb.x, 0.f),
                                              fmaxf(acc[mi][ni][3] + bb.y, 0.f));
                }
            }
        } else {
            int cc0 = bm + row0, cc1 = bm + row1;
            int m0 = -1, m1 = -1;
            float s0 = 0.f, s1 = 0.f;
            if (cc0 < cnt) { m0 = g_slot_m[e * CAPV + cc0]; s0 = g_slot_s[e * CAPV + cc0]; }
            if (cc1 < cnt) { m1 = g_slot_m[e * CAPV + cc1]; s1 = g_slot_s[e * CAPV + cc1]; }
#pragma unroll
            for (int ni = 0; ni < 4; ni++) {
                int colg = bn + wn + ni * 8 + tg * 2;
                float2 bb = *(const float2*)&bp[colg];
                if (m0 >= 0)
                    *(float2*)&g_ya[(size_t)m0 * HIDV + colg] =
                        make_float2(s0 * (acc[mi][ni][0] + bb.x), s0 * (acc[mi][ni][1] + bb.y));
                if (m1 >= 0)
                    *(float2*)&g_ya[(size_t)m1 * HIDV + colg] =
                        make_float2(s1 * (acc[mi][ni][2] + bb.x), s1 * (acc[mi][ni][3] + bb.y));
            }
        }
    }
}

// ---------------- radix select: exact order statistic a[419430] of |logits| ----------------
__global__ void hist_kernel(int shift) {
    __shared__ unsigned h[256];
    int tid = threadIdx.x;
    h[tid] = 0u;
    __syncthreads();
    unsigned prefix = g_prefix;
#pragma unroll
    for (int j = 0; j < 4; j++) {
        int idx = (blockIdx.x * 4 + j) * 256 + tid;
        unsigned u = __float_as_uint(fabsf(g_logits[idx]));
        bool ok = (shift == 24) || ((u >> (shift + 8)) == prefix);
        if (ok) atomicAdd(&h[(u >> shift) & 255], 1u);
    }
    __syncthreads();
    atomicAdd(&g_hist[tid], h[tid]);
}

// parallel pick: 256 threads, one bin each
__global__ void __launch_bounds__(256) pick_kernel(int shift) {
    int tid = threadIdx.x;
    int lane = tid & 31, warp = tid >> 5;
    unsigned c = g_hist[tid];
    unsigned v = c;
#pragma unroll
    for (int off = 1; off < 32; off <<= 1) {
        unsigned o = __shfl_up_sync(0xffffffffu, v, off);
        if (lane >= off) v += o;
    }
    __shared__ unsigned ws[8];
    if (lane == 31) ws[warp] = v;
    __syncthreads();
    unsigned woff = 0;
#pragma unroll
    for (int w = 0; w < 8; w++)
        if (w < warp) woff += ws[w];
    unsigned inc = v + woff;
    unsigned exc = inc - c;
    unsigned r = g_rank;
    if (r < inc && r >= exc) {
        g_rank = r - exc;
        unsigned p = (g_prefix << 8) | (unsigned)tid;
        g_prefix = p;
        if (shift == 0) g_thr = __uint_as_float(p);
    }
    g_hist[tid] = 0u;
}

// ---------------- top-4 (jax tie-break: desc value, asc index) + softmax ----------------
__global__ void __launch_bounds__(128) topk_kernel() {
    int warp = threadIdx.x >> 5;
    int lane = threadIdx.x & 31;
    int n = blockIdx.x * 4 + warp;
    float thr = g_thr;
    const float* row = g_logits + (size_t)n * NE;
    float v[4]; int idx[4];
#pragma unroll
    for (int j = 0; j < 4; j++) {
        int e = lane + j * 32;
        float x = row[e];
        if (fabsf(x) < thr) x = 0.0f;
        v[j] = x; idx[j] = e;
    }
    float tv[4]; int ti[4];
#pragma unroll
    for (int sel = 0; sel < 4; sel++) {
        float bv = v[0]; int bi = idx[0];
#pragma unroll
        for (int j = 1; j < 4; j++)
            if (v[j] > bv || (v[j] == bv && idx[j] < bi)) { bv = v[j]; bi = idx[j]; }
#pragma unroll
        for (int off = 16; off; off >>= 1) {
            float ov = __shfl_xor_sync(0xffffffffu, bv, off);
            int   oi = __shfl_xor_sync(0xffffffffu, bi, off);
            if (ov > bv || (ov == bv && oi < bi)) { bv = ov; bi = oi; }
        }
        tv[sel] = bv; ti[sel] = bi;
#pragma unroll
        for (int j = 0; j < 4; j++)
            if (idx[j] == bi) v[j] = -INFINITY;
    }
    float m = tv[0];
    float ex[4], sum = 0.0f;
#pragma unroll
    for (int k = 0; k < 4; k++) { ex[k] = expf(tv[k] - m); sum += ex[k]; }
    if (lane < 4) {
        g_topi[n * 4 + lane] = ti[lane];
        g_scores[n * 4 + lane] = ex[lane] / sum;
    }
}

// ---------------- xeff[n,d] = x[n,d] * sum_k s_k * diag[e_k,d] ----------------
__global__ void __launch_bounds__(256) xeff_kernel(const float* __restrict__ x,
                                                   const float* __restrict__ diag) {
    int n = blockIdx.x;
    __shared__ int se[4];
    __shared__ float ss[4];
    if (threadIdx.x < 4) {
        se[threadIdx.x] = g_topi[n * 4 + threadIdx.x];
        ss[threadIdx.x] = g_scores[n * 4 + threadIdx.x];
    }
    __syncthreads();
    const float* d0 = diag + (size_t)se[0] * DIMV;
    const float* d1 = diag + (size_t)se[1] * DIMV;
    const float* d2 = diag + (size_t)se[2] * DIMV;
    const float* d3 = diag + (size_t)se[3] * DIMV;
    float s0 = ss[0], s1 = ss[1], s2 = ss[2], s3 = ss[3];
#pragma unroll
    for (int i = 0; i < 4; i++) {
        int d = threadIdx.x + i * 256;
        float eff = s0 * d0[d] + s1 * d1[d] + s2 * d2[d] + s3 * d3[d];
        g_xeff[(size_t)n * DIMV + d] = x[(size_t)n * DIMV + d] * eff;
    }
}

// ---------------- deterministic capacity positions (ballot scan, matches cumsum order) -----
__global__ void __launch_bounds__(256) pos_kernel() {
    int e = blockIdx.x;
    int tid = threadIdx.x;
    int lane = tid & 31, warp = tid >> 5;
    __shared__ int swc[8];
    int base = 0;
    for (int chunk = 0; chunk < M_ASSIGN / 256; chunk++) {
        int m = chunk * 256 + tid;
        int flag = (g_topi[m] == e) ? 1 : 0;
        unsigned mask = __ballot_sync(0xffffffffu, flag);
        int wcnt = __popc(mask);
        int wpre = __popc(mask & ((1u << lane) - 1u));
        if (lane == 0) swc[warp] = wcnt;
        __syncthreads();
        int woff = 0, tot = 0;
#pragma unroll
        for (int w = 0; w < 8; w++) {
            int cw = swc[w];
            if (w < warp) woff += cw;
            tot += cw;
        }
        if (flag) {
            int pos = base + woff + wpre;
            g_pos[m] = pos;
            if (pos < CAPV) {
                g_slot_tok[e * CAPV + pos] = m >> 2;
                g_slot_m[e * CAPV + pos] = m;
                g_slot_s[e * CAPV + pos] = g_scores[m];
            }
        }
        base += tot;
        __syncthreads();
    }
    if (tid == 0) g_cnt[e] = (base < CAPV) ? base : CAPV;
}

// ---------------- host ----------------
extern "C" void kernel_launch(void* const* d_in, const int* in_sizes, int n_in,
                              void* d_out, int out_size) {
    const float* x    = (const float*)d_in[0];
    const float* Wr   = (const float*)d_in[1];
    const float* br   = (const float*)d_in[2];
    const float* diag = (const float*)d_in[3];
    const float* Wp   = (const float*)d_in[4];
    const float* bp   = (const float*)d_in[5];
    const float* W1   = (const float*)d_in[6];
    const float* b1   = (const float*)d_in[7];
    const float* W2   = (const float*)d_in[8];
    const float* b2   = (const float*)d_in[9];
    float* out = (float*)d_out;

    float* p_logits = nullptr;
    float* p_xeff = nullptr;
    float* p_h = nullptr;
    cudaGetSymbolAddress((void**)&p_logits, g_logits);
    cudaGetSymbolAddress((void**)&p_xeff, g_xeff);
    cudaGetSymbolAddress((void**)&p_h, g_h);

    init_kernel<<<1, 256>>>();

    // router logits (exact fp32 — discrete decisions depend on these), 128 blocks
    router_kernel<<<dim3(NE / 64, N_TOK / 64), 256>>>(x, Wr, br, p_logits);

    // exact order statistic a[419430] of |logits|
    for (int shift = 24; shift >= 0; shift -= 8) {
        hist_kernel<<<512, 256>>>(shift);
        pick_kernel<<<1, 256>>>(shift);
    }

    topk_kernel<<<N_TOK / 4, 128>>>();
    xeff_kernel<<<N_TOK, 256>>>(x, diag);
    pos_kernel<<<NE, 256>>>();

    // LoRA down: h = relu(x_gathered @ W1^T + b1)
    mma_gemm_kernel<1, DIMV><<<dim3(1, CAPV / 128, NE), 256>>>(x, W1, b1, p_h, RNK);

    // LoRA up: ya[m] = s * (h @ W2^T + b2), token-major
    mma_gemm_kernel<2, RNK><<<dim3(HIDV / 128, CAPV / 128, NE), 256>>>(p_h, W2, b2, nullptr, HIDV);

    // diag path + fused combine: out = xeff @ Wp^T + bp + sum_k ya[4n+k]
    mma_gemm_kernel<0, DIMV><<<dim3(HIDV / 128, N_TOK / 128), 256>>>(p_xeff, Wp, bp, out, HIDV);
}